// round 17
// baseline (speedup 1.0000x reference)
#include <cuda_runtime.h>
#include <cuda_bf16.h>
#include <cstdint>

// Problem constants
#define T_TOTAL 512
#define T_STEPS 511     // reference output uses H[-2] = h after step index 510
#define B_SZ    64
#define D_IN    256
#define HID     1024
#define OUT_SZ  256
#define GROUP_CTAS 32   // CTAs per bb exchange group
#define ROUNDS   512    // 1 init + 511 steps -> arrivals per CTA per launch

// Scratch (static __device__ — no allocations allowed)
__device__ float g_P[(size_t)T_STEPS * HID * B_SZ];   // [t][j][b]  ~134 MB
__device__ float g_h[2][HID * B_SZ];                  // [j][b] double buffer

// one counting-barrier line per bb group (zero-init; monotone: each launch
// adds exactly GROUP_CTAS*ROUNDS, so base = floor(cnt / (32*512)) * (32*512)
// is launch-invariant even if CTAs read it at slightly different times).
__device__ __align__(128) unsigned long long g_cnt[4 * 16];

// ---------------- f32x2 packed helpers (sm_103a) ----------------
__device__ __forceinline__ unsigned long long pack2(float a, float b) {
    unsigned long long r;
    asm("mov.b64 %0, {%1, %2};" : "=l"(r) : "f"(a), "f"(b));
    return r;
}
__device__ __forceinline__ float2 unpack2(unsigned long long v) {
    float2 r;
    asm("mov.b64 {%0, %1}, %2;" : "=f"(r.x), "=f"(r.y) : "l"(v));
    return r;
}
__device__ __forceinline__ void ffma2(unsigned long long& acc,
                                      unsigned long long a,
                                      unsigned long long b) {
    asm("fma.rn.f32x2 %0, %1, %2, %0;" : "+l"(acc) : "l"(a), "l"(b));
}
__device__ __forceinline__ void add2(unsigned long long& acc, unsigned long long v) {
    asm("add.rn.f32x2 %0, %0, %1;" : "+l"(acc) : "l"(v));
}
// hardware tanh (MUFU.TANH, sm_75+)
__device__ __forceinline__ float tanh_approx(float x) {
    float r;
    asm("tanh.approx.f32 %0, %1;" : "=f"(r) : "f"(x));
    return r;
}
// L1-bypassing vector load (cross-SM coherent at L2) for the h ring buffer
__device__ __forceinline__ float4 ldcg4(const float4* p) {
    float4 v;
    asm volatile("ld.global.cg.v4.f32 {%0,%1,%2,%3}, [%4];"
                 : "=f"(v.x), "=f"(v.y), "=f"(v.z), "=f"(v.w) : "l"(p));
    return v;
}
__device__ __forceinline__ unsigned long long ld_acquire(const unsigned long long* p) {
    unsigned long long v;
    asm volatile("ld.acquire.gpu.global.u64 %0, [%1];" : "=l"(v) : "l"(p) : "memory");
    return v;
}
__device__ __forceinline__ void red_add_release(unsigned long long* p,
                                                unsigned long long v) {
    asm volatile("red.release.gpu.global.add.u64 [%0], %1;"
                 :: "l"(p), "l"(v) : "memory");
}

// ---------------- precompute: P[t][j][b] = sum_d x[t][b][d]*Wx[d][j] + bias[j] --------
// r14/r16 version (best measured: 494us). x staged at ODD row stride 65.
__global__ __launch_bounds__(256, 4) void precompute_kernel(
    const float* __restrict__ x, const float* __restrict__ Wx,
    const float* __restrict__ bias)
{
    __shared__ __align__(16) float xs0[64 * 65 + 4];  // [b][d]  ODD stride 65
    __shared__ __align__(16) float ws[64 * 64];       // [d][j]  float4-accessed

    const int t  = blockIdx.y;
    const int jb = blockIdx.x;
    const int tid = threadIdx.x;
    const int jt = tid & 15;
    const int bt = tid >> 4;

    const float4* x4  = (const float4*)x;
    const float4* Wx4 = (const float4*)Wx;

    unsigned long long acc[4][2];
#pragma unroll
    for (int jj = 0; jj < 4; jj++) { acc[jj][0] = 0ull; acc[jj][1] = 0ull; }

    for (int dt = 0; dt < 4; dt++) {
#pragma unroll
        for (int i = 0; i < 4; i++) {
            int idx = tid + i * 256;
            int b = idx >> 4, q = idx & 15;
            float4 v = x4[(size_t)t * 4096 + b * 64 + dt * 16 + q];
            float* dst = &xs0[b * 65 + q * 4];
            dst[0] = v.x; dst[1] = v.y; dst[2] = v.z; dst[3] = v.w;
        }
#pragma unroll
        for (int i = 0; i < 4; i++) {
            int idx = tid + i * 256;
            int row = idx >> 4, q = idx & 15;
            *(float4*)&ws[row * 64 + q * 4] =
                Wx4[(size_t)(dt * 64 + row) * 256 + jb * 16 + q];
        }
        __syncthreads();

        const float* xr = &xs0[bt * 4 * 65];
#pragma unroll 8
        for (int dd = 0; dd < 64; dd++) {
            unsigned long long xv0 = pack2(xr[dd], xr[dd + 65]);
            unsigned long long xv1 = pack2(xr[dd + 130], xr[dd + 195]);
            float4 wv = *(const float4*)&ws[dd * 64 + jt * 4];
            unsigned long long w0 = pack2(wv.x, wv.x);
            unsigned long long w1 = pack2(wv.y, wv.y);
            unsigned long long w2 = pack2(wv.z, wv.z);
            unsigned long long w3 = pack2(wv.w, wv.w);
            ffma2(acc[0][0], xv0, w0); ffma2(acc[0][1], xv1, w0);
            ffma2(acc[1][0], xv0, w1); ffma2(acc[1][1], xv1, w1);
            ffma2(acc[2][0], xv0, w2); ffma2(acc[2][1], xv1, w2);
            ffma2(acc[3][0], xv0, w3); ffma2(acc[3][1], xv1, w3);
        }
        __syncthreads();
    }

    const int b0 = bt * 4;
#pragma unroll
    for (int jj = 0; jj < 4; jj++) {
        int j = jb * 64 + jt * 4 + jj;
        float bj = bias[j];
        float2 a0 = unpack2(acc[jj][0]);
        float2 a1 = unpack2(acc[jj][1]);
        float4 o = make_float4(a0.x + bj, a0.y + bj, a1.x + bj, a1.y + bj);
        *(float4*)&g_P[((size_t)t * HID + j) * B_SZ + b0] = o;
    }
}

// ---------------- persistent recurrence kernel (r16 + packed f32x2 epilogue) ----
// grid (32 jb, 4 bb) = 128 CTAs, 512 threads = 16 warps. All CTAs resident.
// Wh slice [1024 k][32 j] in smem for the whole kernel (128 KB).
// Sync: counting barrier (red.add.release arrive, tid0 polls w/ nanosleep 32).
// h slice in 2 pipelined 32k chunks; P register double-buffered (float2 now).
// Epilogue: 256 threads reduce 2 outputs each via LDS.64 + add.rn.f32x2
// (halves reduction issue volume + L1 wavefronts on the serial tail).
__global__ __launch_bounds__(512) void rnn_persistent_kernel(const float* __restrict__ Wh)
{
    extern __shared__ float smem[];
    float* whs    = smem;            // [1024 k][32 j]        = 32768 floats (128 KB)
    float* hstage = smem + 32768;    // [16 warp][1024]       = 16384 floats (64 KB)

    const int tid = threadIdx.x;
    const int w   = tid >> 5;
    const int l   = tid & 31;
    const int jp  = l & 15;            // j pair: j_local = jp*2 + {0,1}
    const int bh  = l >> 4;            // b half: b_local = bh*8 + {0..7}
    const int jb  = blockIdx.x;        // 32 blocks of 32 j
    const int bb  = blockIdx.y;        // 4 blocks of 16 b

    unsigned long long* const cnt = &g_cnt[bb * 16];
    const unsigned long long per_launch =
        (unsigned long long)GROUP_CTAS * (unsigned long long)ROUNDS;
    const unsigned long long base = (*cnt / per_launch) * per_launch;

    // ---- load Wh slice into smem once: whs[k*32 + jl] ----
    {
        const float4* wh4  = (const float4*)Wh;    // Wh[k][j], row = 256 f4
        float4*       whs4 = (float4*)whs;         // row = 8 f4
#pragma unroll
        for (int i = 0; i < 16; i++) {
            int idx = tid + i * 512;               // 8192 float4
            int k = idx >> 3, q = idx & 7;
            whs4[k * 8 + q] = wh4[(size_t)k * 256 + jb * 8 + q];
        }
    }
    // ---- zero h0 slice, arrive round 1 ----
    {
        int jl = tid >> 4, bl = tid & 15;
        g_h[0][(jb * 32 + jl) * B_SZ + bb * 16 + bl] = 0.f;
    }
    __syncthreads();
    if (tid == 0) red_add_release(cnt, 1ULL);

    const int k0w = w * 64;
    float* hst = hstage + w * 1024;

    // epilogue ownership: thread tid < 256 handles outputs o2 = 2*tid, 2*tid+1
    // (b-consecutive pair). jl = o2>>4, bl = o2&15 (even).
    const int eo = tid * 2;
    const int e_jl = eo >> 4;
    const int e_bl = eo & 15;
    const float* pptr0 =
        &g_P[((size_t)(jb * 32 + e_jl)) * B_SZ + bb * 16 + e_bl];
    float* const hn_base0 = &g_h[0][(jb * 32 + e_jl) * B_SZ + bb * 16 + e_bl];
    float* const hn_base1 = &g_h[1][(jb * 32 + e_jl) * B_SZ + bb * 16 + e_bl];
    const bool epi = (tid < 256);

    // per-lane chunk staging index math: 32k x 16b chunk = 128 f4, 4 per lane
    const int c_kk[4] = { (l) >> 2, (l + 32) >> 2, (l + 64) >> 2, (l + 96) >> 2 };
    const int c_q[4]  = { (l) & 3,  (l + 32) & 3,  (l + 64) & 3,  (l + 96) & 3  };

    // P double-buffer (float2): load P[0] up front
    float2 pval = make_float2(0.f, 0.f);
    if (epi) pval = *(const float2*)pptr0;

    for (int t = 0; t < T_STEPS; t++) {
        const float4* hp4 = (const float4*)g_h[t & 1];   // h[k][b], row = 16 f4

        // ---- wait for round t+1 (everyone published h_t) ----
        if (tid == 0) {
            const unsigned long long need =
                base + (unsigned long long)GROUP_CTAS * (unsigned long long)(t + 1);
            while (ld_acquire(cnt) < need) { __nanosleep(32); }
        }
        __syncthreads();

        // ---- chunk A load (k0w .. k0w+32) ----
        float4 ha[4];
#pragma unroll
        for (int i = 0; i < 4; i++)
            ha[i] = ldcg4(&hp4[(size_t)(k0w + c_kk[i]) * 16 + bb * 4 + c_q[i]]);
#pragma unroll
        for (int i = 0; i < 4; i++)
            *(float4*)&hst[c_kk[i] * 16 + c_q[i] * 4] = ha[i];
        __syncwarp();

        // ---- chunk B load issued (k0w+32 .. k0w+64), drains under compute A ----
        float4 hb[4];
#pragma unroll
        for (int i = 0; i < 4; i++)
            hb[i] = ldcg4(&hp4[(size_t)(k0w + 32 + c_kk[i]) * 16 + bb * 4 + c_q[i]]);

        // prefetch P for next step (register-carried across the barrier)
        float2 pnext = make_float2(0.f, 0.f);
        if (epi && (t + 1 < T_STEPS))
            pnext = *(const float2*)(pptr0 + (size_t)(t + 1) * (HID * B_SZ));

        unsigned long long acc[2][4];
#pragma unroll
        for (int jj = 0; jj < 2; jj++)
#pragma unroll
            for (int p = 0; p < 4; p++) acc[jj][p] = 0ull;

        const float* wrow = whs + (size_t)k0w * 32;

        // ---- compute chunk A ----
#pragma unroll
        for (int kk = 0; kk < 32; kk++) {
            ulonglong2 hv01 = *(const ulonglong2*)&hst[kk * 16 + bh * 8];
            ulonglong2 hv23 = *(const ulonglong2*)&hst[kk * 16 + bh * 8 + 4];
            float2 wp = *(const float2*)&wrow[kk * 32 + jp * 2];
            unsigned long long w0 = pack2(wp.x, wp.x);
            unsigned long long w1 = pack2(wp.y, wp.y);
            ffma2(acc[0][0], hv01.x, w0);
            ffma2(acc[0][1], hv01.y, w0);
            ffma2(acc[0][2], hv23.x, w0);
            ffma2(acc[0][3], hv23.y, w0);
            ffma2(acc[1][0], hv01.x, w1);
            ffma2(acc[1][1], hv01.y, w1);
            ffma2(acc[1][2], hv23.x, w1);
            ffma2(acc[1][3], hv23.y, w1);
        }

        // ---- stage chunk B, compute it ----
#pragma unroll
        for (int i = 0; i < 4; i++)
            *(float4*)&hst[(32 + c_kk[i]) * 16 + c_q[i] * 4] = hb[i];
        __syncwarp();

#pragma unroll
        for (int kk = 32; kk < 64; kk++) {
            ulonglong2 hv01 = *(const ulonglong2*)&hst[kk * 16 + bh * 8];
            ulonglong2 hv23 = *(const ulonglong2*)&hst[kk * 16 + bh * 8 + 4];
            float2 wp = *(const float2*)&wrow[kk * 32 + jp * 2];
            unsigned long long w0 = pack2(wp.x, wp.x);
            unsigned long long w1 = pack2(wp.y, wp.y);
            ffma2(acc[0][0], hv01.x, w0);
            ffma2(acc[0][1], hv01.y, w0);
            ffma2(acc[0][2], hv23.x, w0);
            ffma2(acc[0][3], hv23.y, w0);
            ffma2(acc[1][0], hv01.x, w1);
            ffma2(acc[1][1], hv01.y, w1);
            ffma2(acc[1][2], hv23.x, w1);
            ffma2(acc[1][3], hv23.y, w1);
        }

        // write k-partials into own warp region (b-consecutive packing kept)
#pragma unroll
        for (int jj = 0; jj < 2; jj++) {
            int o = (jp * 2 + jj) * 16 + bh * 8;
            float2 a0 = unpack2(acc[jj][0]), a1 = unpack2(acc[jj][1]);
            float2 a2 = unpack2(acc[jj][2]), a3 = unpack2(acc[jj][3]);
            *(float4*)&hst[o]     = make_float4(a0.x, a0.y, a1.x, a1.y);
            *(float4*)&hst[o + 4] = make_float4(a2.x, a2.y, a3.x, a3.y);
        }
        __syncthreads();

        // packed epilogue: 256 threads, 2 outputs each (LDS.64 + f32x2 adds)
        if (epi) {
            unsigned long long s = 0ull;
#pragma unroll
            for (int ww = 0; ww < 16; ww++)
                add2(s, *(const unsigned long long*)&hstage[ww * 1024 + eo]);
            float2 sv = unpack2(s);
            float2 hv;
            hv.x = tanh_approx(pval.x + sv.x);
            hv.y = tanh_approx(pval.y + sv.y);
            float* hn = ((t + 1) & 1) ? hn_base1 : hn_base0;
            *(float2*)hn = hv;
        }
        __syncthreads();
        if (tid == 0) red_add_release(cnt, 1ULL);   // arrive round t+2

        pval = pnext;
    }
}

// ---------------- final: y[b][o] = sum_j h[j][b]*W2[j][o] + b2[o] ----------------
__global__ __launch_bounds__(128) void final_kernel(
    const float* __restrict__ W2, const float* __restrict__ b2,
    float* __restrict__ out)
{
    __shared__ __align__(16) float hs[128 * 16];
    __shared__ __align__(16) float ws[128 * 32];

    const int tid = threadIdx.x;
    const int ol = tid & 31;
    const int bt = tid >> 5;
    const int ob = blockIdx.x;
    const int bb = blockIdx.y;

    const float* hfin = g_h[T_STEPS & 1];
    const float4* hp4 = (const float4*)hfin;
    const float4* w24 = (const float4*)W2;

    unsigned long long acc0 = 0ull, acc1 = 0ull;

    for (int c = 0; c < 8; c++) {
        const int k0 = c * 128;
#pragma unroll
        for (int i = 0; i < 4; i++) {
            int idx = tid + i * 128; int row = idx >> 2, q = idx & 3;
            *(float4*)&hs[row * 16 + q * 4] = hp4[(size_t)(k0 + row) * 16 + bb * 4 + q];
        }
#pragma unroll
        for (int i = 0; i < 8; i++) {
            int idx = tid + i * 128; int row = idx >> 3, q = idx & 7;
            *(float4*)&ws[row * 32 + q * 4] = w24[(size_t)(k0 + row) * 64 + ob * 8 + q];
        }
        __syncthreads();
#pragma unroll 8
        for (int kk = 0; kk < 128; kk++) {
            ulonglong2 hv = *(const ulonglong2*)&hs[kk * 16 + bt * 4];
            float w = ws[kk * 32 + ol];
            unsigned long long wp = pack2(w, w);
            ffma2(acc0, hv.x, wp);
            ffma2(acc1, hv.y, wp);
        }
        __syncthreads();
    }

    const int o = ob * 32 + ol;
    const int b0 = bb * 16 + bt * 4;
    const float bo = b2[o];
    float2 a0 = unpack2(acc0), a1 = unpack2(acc1);
    out[(b0 + 0) * OUT_SZ + o] = a0.x + bo;
    out[(b0 + 1) * OUT_SZ + o] = a0.y + bo;
    out[(b0 + 2) * OUT_SZ + o] = a1.x + bo;
    out[(b0 + 3) * OUT_SZ + o] = a1.y + bo;
}

// ---------------- launch ----------------
extern "C" void kernel_launch(void* const* d_in, const int* in_sizes, int n_in,
                              void* d_out, int out_size)
{
    const float* x   = (const float*)d_in[0];
    const float* Wx  = (const float*)d_in[1];
    const float* Wh  = (const float*)d_in[2];
    const float* b   = (const float*)d_in[3];
    const float* W2  = (const float*)d_in[4];
    const float* b2  = (const float*)d_in[5];
    float* out = (float*)d_out;

    const int SMEM_BYTES = (32768 + 16384) * 4;   // 192 KB dynamic smem
    static bool attr_done = false;
    if (!attr_done) {
        cudaFuncSetAttribute(rnn_persistent_kernel,
                             cudaFuncAttributeMaxDynamicSharedMemorySize, SMEM_BYTES);
        attr_done = true;
    }

    precompute_kernel<<<dim3(16, T_STEPS), 256>>>(x, Wx, b);
    rnn_persistent_kernel<<<dim3(32, 4), 512, SMEM_BYTES>>>(Wh);
    final_kernel<<<dim3(8, 4), 128>>>(W2, b2, out);
}